// round 9
// baseline (speedup 1.0000x reference)
#include <cuda_runtime.h>
#include <cuda_fp16.h>
#include <cstdint>
#include <cstddef>

#define Nn 50000
#define Ee 800000

// ---------------- scratch (static device globals; no allocation) ----------------
// float accumulators (permuted channel layout p(c)=16t+2nt+j for c=8nt+2t+j)
__device__ float4 g_s4  [Nn * 16];
__device__ float4 g_acc4[Nn * 16];
// fp16 node operands, permuted layout: v, Q=h@(Wsrc*Wa1), P=h@(Wdst*Wa1)
__device__ __align__(16) __half g_vh[Nn * 64];
__device__ __align__(16) __half g_Qh[Nn * 64];
__device__ __align__(16) __half g_Ph[Nn * 64];
// folded weights (fp32, row-major 64x64) + folded bias
__device__ float g_WsA[4096];
__device__ float g_WdA[4096];
__device__ float g_WpA[4096];
__device__ float g_cvec[64];

// ---------------- helpers ----------------
__device__ __forceinline__ uint32_t pack_f16x2(float a, float b) {
    uint32_t w;
    asm("cvt.rn.f16x2.f32 %0, %1, %2;" : "=r"(w) : "f"(b), "f"(a));  // lo=a, hi=b
    return w;
}
__device__ __forceinline__ void pack_hl_f16(float a, float b, uint32_t& h, uint32_t& l) {
    asm("cvt.rn.f16x2.f32 %0, %1, %2;" : "=r"(h) : "f"(b), "f"(a));
    __half2 h2 = *reinterpret_cast<__half2*>(&h);
    float la = a - __half2float(h2.x);
    float lb = b - __half2float(h2.y);
    asm("cvt.rn.f16x2.f32 %0, %1, %2;" : "=r"(l) : "f"(lb), "f"(la));
}
__device__ __forceinline__ float2 h2f2(uint32_t w) {
    __half2 h = *reinterpret_cast<__half2*>(&w);
    return make_float2(__half2float(h.x), __half2float(h.y));
}
__device__ __forceinline__ void red4(float4* p, float a, float b, float c, float d) {
    asm volatile("red.global.add.v4.f32 [%0], {%1, %2, %3, %4};"
                 :: "l"(p), "f"(a), "f"(b), "f"(c), "f"(d) : "memory");
}
__device__ __forceinline__ void mma_f16(float* d, const uint32_t* a, uint2 b) {
    asm volatile(
        "mma.sync.aligned.m16n8k16.row.col.f32.f16.f16.f32 "
        "{%0,%1,%2,%3},{%4,%5,%6,%7},{%8,%9},{%0,%1,%2,%3};"
        : "+f"(d[0]), "+f"(d[1]), "+f"(d[2]), "+f"(d[3])
        : "r"(a[0]), "r"(a[1]), "r"(a[2]), "r"(a[3]), "r"(b.x), "r"(b.y));
}
__device__ __forceinline__ void gemm1p(float* D, const uint32_t* Ah,
                                       const uint2* __restrict__ bfH, int lane) {
#pragma unroll
    for (int kt = 0; kt < 4; kt++)
#pragma unroll
        for (int nt = 0; nt < 8; nt++)
            mma_f16(D + nt * 4, Ah + kt * 4, bfH[(kt * 8 + nt) * 32 + lane]);
}
__device__ __forceinline__ void gemm2p(float* D, const uint32_t* Ah,
                                       const uint2* __restrict__ bfH,
                                       const uint2* __restrict__ bfL, int lane) {
#pragma unroll
    for (int kt = 0; kt < 4; kt++)
#pragma unroll
        for (int nt = 0; nt < 8; nt++) {
            mma_f16(D + nt * 4, Ah + kt * 4, bfH[(kt * 8 + nt) * 32 + lane]);
            mma_f16(D + nt * 4, Ah + kt * 4, bfL[(kt * 8 + nt) * 32 + lane]);
        }
}
__device__ __forceinline__ void gemm3p(float* D, const uint32_t* Ah, const uint32_t* Al,
                                       const uint2* __restrict__ bfH,
                                       const uint2* __restrict__ bfL, int lane) {
#pragma unroll
    for (int kt = 0; kt < 4; kt++)
#pragma unroll
        for (int nt = 0; nt < 8; nt++) {
            uint2 bh = bfH[(kt * 8 + nt) * 32 + lane];
            mma_f16(D + nt * 4, Ah + kt * 4, bh);
            mma_f16(D + nt * 4, Al + kt * 4, bh);
            mma_f16(D + nt * 4, Ah + kt * 4, bfL[(kt * 8 + nt) * 32 + lane]);
        }
}

// build B fragments from 64x64 row-major W (logical indices); dstL may be null
__device__ __forceinline__ void build_bf(uint2* dstH, uint2* dstL,
                                         const float* __restrict__ W,
                                         int tid, int nth) {
    for (int i = tid; i < 1024; i += nth) {
        int kt = i >> 8, nt = (i >> 5) & 7, lane = i & 31;
        int g = lane >> 2, t = lane & 3;
        int col = 8 * nt + g;
        int k0  = 16 * kt + 2 * t;
        float w00 = W[(k0    ) * 64 + col];
        float w01 = W[(k0 + 1) * 64 + col];
        float w10 = W[(k0 + 8) * 64 + col];
        float w11 = W[(k0 + 9) * 64 + col];
        uint32_t h0, l0, h1, l1;
        pack_hl_f16(w00, w01, h0, l0);
        pack_hl_f16(w10, w11, h1, l1);
        int idx = (kt * 8 + nt) * 32 + lane;
        dstH[idx] = make_uint2(h0, h1);
        if (dstL) dstL[idx] = make_uint2(l0, l1);
    }
}

// ---------------- kernel -1: fold weight products (fp32) ----------------
__global__ __launch_bounds__(256) void fold_kernel(
    const float* __restrict__ Wsrc, const float* __restrict__ Wdst,
    const float* __restrict__ Wp2,  const float* __restrict__ Wa1,
    const float* __restrict__ bp2,  const float* __restrict__ ba1)
{
    int gid = blockIdx.x * blockDim.x + threadIdx.x;
    if (gid < 3 * 4096) {
        int m = gid >> 12;
        int idx = gid & 4095;
        int i = idx >> 6, j = idx & 63;
        const float* A = (m == 0) ? Wsrc : (m == 1) ? Wdst : Wp2;
        float s = 0.f;
        for (int k = 0; k < 64; k++) s = fmaf(A[i * 64 + k], Wa1[k * 64 + j], s);
        float* O = (m == 0) ? g_WsA : (m == 1) ? g_WdA : g_WpA;
        O[idx] = s;
    }
    if (gid < 64) {
        float s = ba1[gid];
        for (int k = 0; k < 64; k++) s = fmaf(bp2[k], Wa1[k * 64 + gid], s);
        g_cvec[gid] = s;
    }
}

// ---------------- kernel 0: init reduction buffers ----------------
__global__ __launch_bounds__(256) void init_kernel() {
    int i = blockIdx.x * blockDim.x + threadIdx.x;
    if (i < Nn * 16) {
        g_s4[i]   = make_float4(0.f, 0.f, 0.f, 0.f);
        g_acc4[i] = make_float4(0.f, 0.f, 0.f, 0.f);
    }
}

// ---------------- kernel 1: node projections (mma; outputs v, Q, P fp16 permuted) ----------------
__global__ __launch_bounds__(256) void node_proj_kernel(
    const float* __restrict__ x,
    const float* __restrict__ Win,  const float* __restrict__ bin,
    const float* __restrict__ Wlin)
{
    extern __shared__ __align__(16) char smem[];
    uint2*  sBF  = (uint2*)smem;                       // 8 x 1024 uint2 = 64KB
    float2* sBin = (float2*)(smem + 65536);
    const int tid = threadIdx.x;

    build_bf(sBF + 0 * 1024, sBF + 1 * 1024, Win,  tid, 256);
    build_bf(sBF + 2 * 1024, sBF + 3 * 1024, Wlin, tid, 256);
    build_bf(sBF + 4 * 1024, sBF + 5 * 1024, (const float*)g_WsA, tid, 256);
    build_bf(sBF + 6 * 1024, sBF + 7 * 1024, (const float*)g_WdA, tid, 256);
    if (tid < 32) sBin[tid] = make_float2(bin[2 * tid], bin[2 * tid + 1]);
    __syncthreads();

    const int lane = tid & 31;
    const int g = lane >> 2, t = lane & 3;

    __half* outs[3] = { g_vh, g_Qh, g_Ph };

    const int nTiles = Nn / 16;  // 3125
    const int wStride = gridDim.x * 8;
    for (int tile = blockIdx.x * 8 + (tid >> 5); tile < nTiles; tile += wStride) {
        const int n0 = tile * 16;

        uint32_t Ah[16];
#pragma unroll
        for (int kt = 0; kt < 4; kt++)
#pragma unroll
            for (int half = 0; half < 2; half++)
#pragma unroll
                for (int h = 0; h < 2; h++) {
                    float2 xx = *(const float2*)&x[(n0 + g + 8 * h) * 64 + 16 * kt + 2 * t + 8 * half];
                    Ah[kt * 4 + h + 2 * half] = pack_f16x2(xx.x, xx.y);
                }

        float D[32];
#pragma unroll
        for (int i = 0; i < 32; i++) D[i] = 0.f;
        gemm2p(D, Ah, sBF + 0 * 1024, sBF + 1 * 1024, lane);

        uint32_t Ah2[16];
#pragma unroll
        for (int nt = 0; nt < 8; nt++) {
            float2 bb = sBin[4 * nt + t];
            int kt = nt >> 1, half = nt & 1, slot = kt * 4 + 2 * half;
            Ah2[slot]     = pack_f16x2(fmaxf(D[nt * 4 + 0] + bb.x, 0.f),
                                       fmaxf(D[nt * 4 + 1] + bb.y, 0.f));
            Ah2[slot + 1] = pack_f16x2(fmaxf(D[nt * 4 + 2] + bb.x, 0.f),
                                       fmaxf(D[nt * 4 + 3] + bb.y, 0.f));
        }

#pragma unroll
        for (int m = 0; m < 3; m++) {
#pragma unroll
            for (int i = 0; i < 32; i++) D[i] = 0.f;
            gemm2p(D, Ah2, sBF + (2 + 2 * m) * 1024, sBF + (3 + 2 * m) * 1024, lane);
            __half* o = outs[m];
#pragma unroll
            for (int ntp = 0; ntp < 4; ntp++) {
                int na = 2 * ntp, nb = na + 1;
                uint2 r0 = make_uint2(pack_f16x2(D[na * 4 + 0], D[na * 4 + 1]),
                                      pack_f16x2(D[nb * 4 + 0], D[nb * 4 + 1]));
                uint2 r8 = make_uint2(pack_f16x2(D[na * 4 + 2], D[na * 4 + 3]),
                                      pack_f16x2(D[nb * 4 + 2], D[nb * 4 + 3]));
                *(uint2*)(o + (n0 + g    ) * 64 + 16 * t + 4 * ntp) = r0;
                *(uint2*)(o + (n0 + g + 8) * 64 + 16 * t + 4 * ntp) = r8;
            }
        }
    }
}

// ---------------- kernel 2: fused edge kernel (folded attention path) ----------------
// smem: 3 B-frag arrays (Wp2 h, WpA h, Wa2 h) + Wp1 + biases
#define ESM_WP1   24576
#define ESM_BP2   25600
#define ESM_CV    25856
#define ESM_BA2   26112
#define ESM_TOTAL 26624

__global__ __launch_bounds__(256, 2) void edge_fused_kernel(
    const float* __restrict__ pos, const int* __restrict__ ei,
    const float* __restrict__ Wp1, const float* __restrict__ bp1,
    const float* __restrict__ Wp2, const float* __restrict__ bp2,
    const float* __restrict__ Wa2, const float* __restrict__ ba2)
{
    extern __shared__ __align__(16) char smem[];
    uint2*  sBF  = (uint2*)smem;
    float4* sWp1 = (float4*)(smem + ESM_WP1);
    float2* sBp2 = (float2*)(smem + ESM_BP2);
    float2* sCv  = (float2*)(smem + ESM_CV);
    float2* sBa2 = (float2*)(smem + ESM_BA2);

    const int tid = threadIdx.x;
    build_bf(sBF + 0 * 1024, (uint2*)0, Wp2,                  tid, 256);
    build_bf(sBF + 1 * 1024, (uint2*)0, (const float*)g_WpA,  tid, 256);
    build_bf(sBF + 2 * 1024, (uint2*)0, Wa2,                  tid, 256);
    if (tid < 64)
        sWp1[tid] = make_float4(Wp1[tid], Wp1[64 + tid], Wp1[128 + tid], bp1[tid]);
    if (tid < 32) {
        sBp2[tid] = make_float2(bp2[2 * tid], bp2[2 * tid + 1]);
        sCv[tid]  = make_float2(g_cvec[2 * tid], g_cvec[2 * tid + 1]);
        sBa2[tid] = make_float2(ba2[2 * tid], ba2[2 * tid + 1]);
    }
    __syncthreads();

    const int lane = tid & 31;
    const int g = lane >> 2, t = lane & 3;

    const uint2* bfP2h = sBF + 0 * 1024;
    const uint2* bfPAh = sBF + 1 * 1024;
    const uint2* bfA2h = sBF + 2 * 1024;

    const int nTiles = Ee / 16;          // 50000
    const int wStride = gridDim.x * 8;

    int tile = blockIdx.x * 8 + (tid >> 5);

    // prefetch first tile's edge data (lanes 0-15 hold one edge each)
    int pS = 0, pD = 0;
    float pr0 = 0.f, pr1 = 0.f, pr2 = 0.f;
    if (tile < nTiles && lane < 16) {
        int e = tile * 16 + lane;
        pS = __ldg(&ei[e]);
        pD = __ldg(&ei[Ee + e]);
        pr0 = __ldg(&pos[pD * 3 + 0]) - __ldg(&pos[pS * 3 + 0]);
        pr1 = __ldg(&pos[pD * 3 + 1]) - __ldg(&pos[pS * 3 + 1]);
        pr2 = __ldg(&pos[pD * 3 + 2]) - __ldg(&pos[pS * 3 + 2]);
    }

    for (; tile < nTiles; tile += wStride) {
        int sn[2], dn[2];
        float rl[2][3];
#pragma unroll
        for (int h = 0; h < 2; h++) {
            int src = g + 8 * h;
            sn[h]   = __shfl_sync(0xffffffffu, pS, src);
            dn[h]   = __shfl_sync(0xffffffffu, pD, src);
            rl[h][0] = __shfl_sync(0xffffffffu, pr0, src);
            rl[h][1] = __shfl_sync(0xffffffffu, pr1, src);
            rl[h][2] = __shfl_sync(0xffffffffu, pr2, src);
        }

        // prefetch next tile's indices early (max latency coverage)
        const int tn = tile + wStride;
        int nS = 0, nD = 0;
        if (tn < nTiles && lane < 16) {
            int e = tn * 16 + lane;
            nS = __ldg(&ei[e]);
            nD = __ldg(&ei[Ee + e]);
        }

        // hoist P/Q gathers (consumed after G2')
        uint4 P0a = __ldg((const uint4*)(g_Ph + dn[0] * 64 + 16 * t));
        uint4 P0b = __ldg((const uint4*)(g_Ph + dn[0] * 64 + 16 * t + 8));
        uint4 Q0a = __ldg((const uint4*)(g_Qh + sn[0] * 64 + 16 * t));
        uint4 Q0b = __ldg((const uint4*)(g_Qh + sn[0] * 64 + 16 * t + 8));
        uint4 P1a = __ldg((const uint4*)(g_Ph + dn[1] * 64 + 16 * t));
        uint4 P1b = __ldg((const uint4*)(g_Ph + dn[1] * 64 + 16 * t + 8));
        uint4 Q1a = __ldg((const uint4*)(g_Qh + sn[1] * 64 + 16 * t));
        uint4 Q1b = __ldg((const uint4*)(g_Qh + sn[1] * 64 + 16 * t + 8));

        // stage 1: u = relu(rel @ Wp1 + bp1) -> A frags (u operand, kept for G1 too)
        uint32_t Au[16];
#pragma unroll
        for (int kt = 0; kt < 4; kt++)
#pragma unroll
            for (int half = 0; half < 2; half++) {
                int c0 = 16 * kt + 2 * t + 8 * half;
                float4 w0 = sWp1[c0];
                float4 w1 = sWp1[c0 + 1];
#pragma unroll
                for (int h = 0; h < 2; h++) {
                    float u0 = fmaxf(fmaf(rl[h][2], w0.z, fmaf(rl[h][1], w0.y,
                               fmaf(rl[h][0], w0.x, w0.w))), 0.f);
                    float u1 = fmaxf(fmaf(rl[h][2], w1.z, fmaf(rl[h][1], w1.y,
                               fmaf(rl[h][0], w1.x, w1.w))), 0.f);
                    Au[kt * 4 + h + 2 * half] = pack_f16x2(u0, u1);
                }
            }

        // G2': h2_pre = u @ WpA
        float Dx[32];
#pragma unroll
        for (int i = 0; i < 32; i++) Dx[i] = 0.f;
        gemm1p(Dx, Au, bfPAh, lane);

        // next tile's pos prefetch (covered by G1/G3)
        if (tn < nTiles && lane < 16) {
            pr0 = __ldg(&pos[nD * 3 + 0]) - __ldg(&pos[nS * 3 + 0]);
            pr1 = __ldg(&pos[nD * 3 + 1]) - __ldg(&pos[nS * 3 + 1]);
            pr2 = __ldg(&pos[nD * 3 + 2]) - __ldg(&pos[nS * 3 + 2]);
        }
        pS = nS; pD = nD;

        // epi-a: Dx += cvec + P[dn] - Q[sn]   (frees P/Q regs)
        {
            uint32_t wP0[8] = {P0a.x, P0a.y, P0a.z, P0a.w, P0b.x, P0b.y, P0b.z, P0b.w};
            uint32_t wQ0[8] = {Q0a.x, Q0a.y, Q0a.z, Q0a.w, Q0b.x, Q0b.y, Q0b.z, Q0b.w};
            uint32_t wP1[8] = {P1a.x, P1a.y, P1a.z, P1a.w, P1b.x, P1b.y, P1b.z, P1b.w};
            uint32_t wQ1[8] = {Q1a.x, Q1a.y, Q1a.z, Q1a.w, Q1b.x, Q1b.y, Q1b.z, Q1b.w};
#pragma unroll
            for (int nt = 0; nt < 8; nt++) {
                float2 cv = sCv[4 * nt + t];
                float2 p0 = h2f2(wP0[nt]), q0 = h2f2(wQ0[nt]);
                float2 p1 = h2f2(wP1[nt]), q1 = h2f2(wQ1[nt]);
                Dx[nt * 4 + 0] += cv.x + p0.x - q0.x;
                Dx[nt * 4 + 1] += cv.y + p0.y - q0.y;
                Dx[nt * 4 + 2] += cv.x + p1.x - q1.x;
                Dx[nt * 4 + 3] += cv.y + p1.y - q1.y;
            }
        }

        // G1: delta_raw = u @ Wp2 (latency hidden; result used only at the end)
        float D1[32];
#pragma unroll
        for (int i = 0; i < 32; i++) D1[i] = 0.f;
        gemm1p(D1, Au, bfP2h, lane);

        // pack delta to fp16 (frees D1)
        uint32_t dltp[16];
#pragma unroll
        for (int nt = 0; nt < 8; nt++) {
            float2 bb = sBp2[4 * nt + t];
            dltp[2 * nt]     = pack_f16x2(D1[nt * 4 + 0] + bb.x, D1[nt * 4 + 1] + bb.y);
            dltp[2 * nt + 1] = pack_f16x2(D1[nt * 4 + 2] + bb.x, D1[nt * 4 + 3] + bb.y);
        }

        // epi-b: h2 = relu(Dx) -> A frags (in place over Au; G1 already consumed u)
#pragma unroll
        for (int nt = 0; nt < 8; nt++) {
            int kt = nt >> 1, half = nt & 1, slot = kt * 4 + 2 * half;
            Au[slot]     = pack_f16x2(fmaxf(Dx[nt * 4 + 0], 0.f), fmaxf(Dx[nt * 4 + 1], 0.f));
            Au[slot + 1] = pack_f16x2(fmaxf(Dx[nt * 4 + 2], 0.f), fmaxf(Dx[nt * 4 + 3], 0.f));
        }

        // v gathers (covered by G3)
        uint4 v0a = __ldg((const uint4*)(g_vh + sn[0] * 64 + 16 * t));
        uint4 v0b = __ldg((const uint4*)(g_vh + sn[0] * 64 + 16 * t + 8));
        uint4 v1a = __ldg((const uint4*)(g_vh + sn[1] * 64 + 16 * t));
        uint4 v1b = __ldg((const uint4*)(g_vh + sn[1] * 64 + 16 * t + 8));

        // G3: logits = h2 @ Wa2
#pragma unroll
        for (int i = 0; i < 32; i++) Dx[i] = 0.f;
        gemm1p(Dx, Au, bfA2h, lane);

        // final epi: e = exp(Dx + ba2); scatter-add s and e*(v + delta)
        uint32_t wv0[8] = {v0a.x, v0a.y, v0a.z, v0a.w, v0b.x, v0b.y, v0b.z, v0b.w};
        uint32_t wv1[8] = {v1a.x, v1a.y, v1a.z, v1a.w, v1b.x, v1b.y, v1b.z, v1b.w};
        float* sp = (float*)g_s4;
        float* ap = (float*)g_acc4;
#pragma unroll
        for (int ntp = 0; ntp < 4; ntp++) {
            int na = 2 * ntp, nb = na + 1;
            float2 ba_a = sBa2[4 * na + t], ba_b = sBa2[4 * nb + t];
            float2 va0 = h2f2(wv0[na]), vb0 = h2f2(wv0[nb]);
            float2 va1 = h2f2(wv1[na]), vb1 = h2f2(wv1[nb]);
            float2 dna0 = h2f2(dltp[2 * na]),     dnb0 = h2f2(dltp[2 * nb]);
            float2 dna1 = h2f2(dltp[2 * na + 1]), dnb1 = h2f2(dltp[2 * nb + 1]);
            // edge 0 (row g)
            float e00 = __expf(Dx[na * 4 + 0] + ba_a.x);
            float e01 = __expf(Dx[na * 4 + 1] + ba_a.y);
            float e02 = __expf(Dx[nb * 4 + 0] + ba_b.x);
            float e03 = __expf(Dx[nb * 4 + 1] + ba_b.y);
            float a00 = e00 * (va0.x + dna0.x);
            float a01 = e01 * (va0.y + dna0.y);
            float a02 = e02 * (vb0.x + dnb0.x);
            float a03 = e03 * (vb0.y + dnb0.y);
            int off0 = dn[0] * 64 + 16 * t + 4 * ntp;
            red4((float4*)(sp + off0), e00, e01, e02, e03);
            red4((float4*)(ap + off0), a00, a01, a02, a03);
            // edge 1 (row g+8)
            float e10 = __expf(Dx[na * 4 + 2] + ba_a.x);
            float e11 = __expf(Dx[na * 4 + 3] + ba_a.y);
            float e12 = __expf(Dx[nb * 4 + 2] + ba_b.x);
            float e13 = __expf(Dx[nb * 4 + 3] + ba_b.y);
            float a10 = e10 * (va1.x + dna1.x);
            float a11 = e11 * (va1.y + dna1.y);
            float a12 = e12 * (vb1.x + dnb1.x);
            float a13 = e13 * (vb1.y + dnb1.y);
            int off1 = dn[1] * 64 + 16 * t + 4 * ntp;
            red4((float4*)(sp + off1), e10, e11, e12, e13);
            red4((float4*)(ap + off1), a10, a11, a12, a13);
        }
    }
}

// ---------------- kernel 3: normalize + lin_out + relu (mma) ----------------
__global__ __launch_bounds__(256) void node_out_kernel(
    const float* __restrict__ Wout, const float* __restrict__ bout,
    float* __restrict__ out)
{
    extern __shared__ __align__(16) char smem[];
    uint2*  sBF  = (uint2*)smem;                  // Wout hi + lo = 16KB
    float2* sB   = (float2*)(smem + 16384);
    const int tid = threadIdx.x;
    build_bf(sBF, sBF + 1024, Wout, tid, 256);
    if (tid < 32) sB[tid] = make_float2(bout[2 * tid], bout[2 * tid + 1]);
    __syncthreads();

    const int lane = tid & 31;
    const int g = lane >> 2, t = lane & 3;
    const float* accp = (const float*)g_acc4;
    const float* ssp  = (const float*)g_s4;

    const int nTiles = Nn / 16;  // 3125
    const int wStride = gridDim.x * 8;
    for (int tile = blockIdx.x * 8 + (tid >> 5); tile < nTiles; tile += wStride) {
        const int n0 = tile * 16;

        float rg0[16], rg1[16];
#pragma unroll
        for (int q = 0; q < 4; q++) {
            float4 a0 = *(const float4*)(accp + (n0 + g) * 64 + 16 * t + 4 * q);
            float4 s0 = *(const float4*)(ssp  + (n0 + g) * 64 + 16 * t + 4 * q);
            rg0[4 * q + 0] = a0.x / (s0.x + 1e-16f);
            rg0[4 * q + 1] = a0.y / (s0.y + 1e-16f);
            rg0[4 * q + 2] = a0.z / (s0.z + 1e-16f);
            rg0[4 * q + 3] = a0.w / (s0.w + 1e-16f);
            float4 a1 = *(const float4*)(accp + (n0 + g + 8) * 64 + 16 * t + 4 * q);
            float4 s1 = *(const float4*)(ssp  + (n0 + g + 8) * 64 + 16 * t + 4 * q);
            rg1[4 * q + 0] = a1.x / (s1.x + 1e-16f);
            rg1[4 * q + 1] = a1.y / (s1.y + 1e-16f);
            rg1[4 * q + 2] = a1.z / (s1.z + 1e-16f);
            rg1[4 * q + 3] = a1.w / (s1.w + 1e-16f);
        }

        uint32_t Ah[16], Al[16];
#pragma unroll
        for (int nt = 0; nt < 8; nt++) {
            int kt = nt >> 1, half = nt & 1, slot = kt * 4 + 2 * half;
            pack_hl_f16(rg0[2 * nt], rg0[2 * nt + 1], Ah[slot],     Al[slot]);
            pack_hl_f16(rg1[2 * nt], rg1[2 * nt + 1], Ah[slot + 1], Al[slot + 1]);
        }

        float D[32];
#pragma unroll
        for (int i = 0; i < 32; i++) D[i] = 0.f;
        gemm3p(D, Ah, Al, sBF, sBF + 1024, lane);

#pragma unroll
        for (int nt = 0; nt < 8; nt++) {
            int c0 = 8 * nt + 2 * t;
            float2 bb = sB[4 * nt + t];
            *(float2*)&out[(n0 + g    ) * 64 + c0] =
                make_float2(fmaxf(D[nt * 4 + 0] + bb.x, 0.f),
                            fmaxf(D[nt * 4 + 1] + bb.y, 0.f));
            *(float2*)&out[(n0 + g + 8) * 64 + c0] =
                make_float2(fmaxf(D[nt * 4 + 2] + bb.x, 0.f),
                            fmaxf(D[nt * 4 + 3] + bb.y, 0.f));
        }
    }
}

// ---------------- launch ----------------
extern "C" void kernel_launch(void* const* d_in, const int* in_sizes, int n_in,
                              void* d_out, int out_size)
{
    const float* x    = (const float*)d_in[0];
    const float* pos  = (const float*)d_in[1];
    const int*   ei   = (const int*)  d_in[2];
    const float* Win  = (const float*)d_in[3];
    const float* bin  = (const float*)d_in[4];
    const float* Wlin = (const float*)d_in[5];
    const float* Wsrc = (const float*)d_in[6];
    const float* Wdst = (const float*)d_in[7];
    const float* Wp1  = (const float*)d_in[8];
    const float* bp1  = (const float*)d_in[9];
    const float* Wp2  = (const float*)d_in[10];
    const float* bp2  = (const float*)d_in[11];
    const float* Wa1  = (const float*)d_in[12];
    const float* ba1  = (const float*)d_in[13];
    const float* Wa2  = (const float*)d_in[14];
    const float* ba2  = (const float*)d_in[15];
    const float* Wout = (const float*)d_in[16];
    const float* bout = (const float*)d_in[17];

    const int projSmem = 65536 + 256;
    const int outSmem  = 16384 + 256;
    cudaFuncSetAttribute(node_proj_kernel,  cudaFuncAttributeMaxDynamicSharedMemorySize, projSmem);
    cudaFuncSetAttribute(edge_fused_kernel, cudaFuncAttributeMaxDynamicSharedMemorySize, ESM_TOTAL);
    cudaFuncSetAttribute(node_out_kernel,   cudaFuncAttributeMaxDynamicSharedMemorySize, outSmem);

    fold_kernel<<<48, 256>>>(Wsrc, Wdst, Wp2, Wa1, bp2, ba1);
    init_kernel<<<(Nn * 16 + 255) / 256, 256>>>();
    node_proj_kernel<<<391, 256, projSmem>>>(x, Win, bin, Wlin);
    edge_fused_kernel<<<296, 256, ESM_TOTAL>>>(pos, ei, Wp1, bp1, Wp2, bp2,
                                               Wa2, ba2);
    node_out_kernel<<<391, 256, outSmem>>>(Wout, bout, (float*)d_out);
}